// round 11
// baseline (speedup 1.0000x reference)
#include <cuda_runtime.h>

// Closed form (derived R0): theta_i = x[b,i]+w[i], c_i = cos(2*theta_i)
//   out[b] = { c1*c2*c3, c0*c1, c0*c1*c2, c0*c1*c2*c3 }
//
// R11: R8 flat skeleton + cross-wave L2 prefetch. DRAM read rate has been
// pinned at ~3 TB/s across 7 designs = per-SM outstanding-sector (MSHR)
// ceiling, schedule-invariant. prefetch.global.L2 is fire-and-forget (no
// writeback/scoreboard/MSHR-return slot), so wave-1 CTAs pull wave-2's
// input into L2 ahead of time; wave-2 LDGs then hit L2 (234cyc) instead of
// DRAM (~600cyc). One prefetch per 128B line ((i&7)==0), PDIST = concurrent
// resident threads.

#define PDIST 303104   // ~148 SMs x 2048 resident threads = one wave of float4s

__device__ __forceinline__ float4 proc(float4 xv, float w0, float w1,
                                       float w2, float w3)
{
    float c0 = __cosf(fmaf(2.0f, xv.x, w0));
    float c1 = __cosf(fmaf(2.0f, xv.y, w1));
    float c2 = __cosf(fmaf(2.0f, xv.z, w2));
    float c3 = __cosf(fmaf(2.0f, xv.w, w3));
    float t01  = c0 * c1;
    float t012 = t01 * c2;
    float4 o;
    o.x = c1 * c2 * c3;
    o.y = t01;
    o.z = t012;
    o.w = t012 * c3;
    return o;
}

__global__ void __launch_bounds__(256)
hilbert_flat_pf(const float4* __restrict__ x4,
                const float* __restrict__ w,
                float4* __restrict__ out4, int n)
{
    int i = blockIdx.x * blockDim.x + threadIdx.x;
    if (i >= n) return;

    // fire-and-forget prefetch for the next occupancy wave (1 per 128B line)
    int pf = i + PDIST;
    if ((i & 7) == 0 && pf < n)
        asm volatile("prefetch.global.L2 [%0];" :: "l"(x4 + pf));

    float w0 = 2.0f * w[0], w1 = 2.0f * w[1];
    float w2 = 2.0f * w[2], w3 = 2.0f * w[3];

    out4[i] = proc(x4[i], w0, w1, w2, w3);
}

extern "C" void kernel_launch(void* const* d_in, const int* in_sizes, int n_in,
                              void* d_out, int out_size)
{
    const float* x = (const float*)d_in[0];
    const float* w = (const float*)d_in[1];
    int nx = in_sizes[0];
    if (n_in >= 2 && in_sizes[0] < in_sizes[1]) {
        x = (const float*)d_in[1];
        w = (const float*)d_in[0];
        nx = in_sizes[1];
    }

    int n = nx / 4;  // float4 count (= batch)
    int threads = 256;
    int blocks = (n + threads - 1) / threads;   // 8192 for BATCH=2^21

    hilbert_flat_pf<<<blocks, threads>>>(
        (const float4*)x, w, (float4*)d_out, n);
}

// round 12
// speedup vs baseline: 1.0816x; 1.0816x over previous
#include <cuda_runtime.h>

// Closed form of the 4-qubit circuit (derived R0, verified):
//   theta_i = x[b,i] + w[i],  c_i = cos(2*theta_i)
//   out[b] = { c1*c2*c3, c0*c1, c0*c1*c2, c0*c1*c2*c3 }
//
// FINAL (R8 keeper, 10.688us best of 8 designs): flat 1-float4-per-thread.
// Series conclusion: kernel is latency-exposure bound (T_ovh ~2.7us launch/
// ramp + ~8us streaming phase limited by L2/DRAM round-trip exposure).
// Invariant to: work-per-thread (1..8), MLP shape, LDG.128 vs LDG.256 vs
// cp.async, L2 evict hints, cross-wave prefetch. All pipes <=40% at the
// floor. Simplest design wins.

__device__ __forceinline__ float4 proc(float4 xv, float w0, float w1,
                                       float w2, float w3)
{
    float c0 = __cosf(fmaf(2.0f, xv.x, w0));
    float c1 = __cosf(fmaf(2.0f, xv.y, w1));
    float c2 = __cosf(fmaf(2.0f, xv.z, w2));
    float c3 = __cosf(fmaf(2.0f, xv.w, w3));
    float t01  = c0 * c1;
    float t012 = t01 * c2;
    float4 o;
    o.x = c1 * c2 * c3;
    o.y = t01;
    o.z = t012;
    o.w = t012 * c3;
    return o;
}

__global__ void __launch_bounds__(256)
hilbert_flat(const float4* __restrict__ x4,
             const float* __restrict__ w,
             float4* __restrict__ out4, int n)
{
    int i = blockIdx.x * blockDim.x + threadIdx.x;
    if (i >= n) return;
    float w0 = 2.0f * w[0], w1 = 2.0f * w[1];
    float w2 = 2.0f * w[2], w3 = 2.0f * w[3];
    out4[i] = proc(x4[i], w0, w1, w2, w3);
}

extern "C" void kernel_launch(void* const* d_in, const int* in_sizes, int n_in,
                              void* d_out, int out_size)
{
    const float* x = (const float*)d_in[0];
    const float* w = (const float*)d_in[1];
    int nx = in_sizes[0];
    if (n_in >= 2 && in_sizes[0] < in_sizes[1]) {
        x = (const float*)d_in[1];
        w = (const float*)d_in[0];
        nx = in_sizes[1];
    }

    int n = nx / 4;  // float4 count (= batch)
    int threads = 256;
    int blocks = (n + threads - 1) / threads;   // 8192 for BATCH=2^21

    hilbert_flat<<<blocks, threads>>>(
        (const float4*)x, w, (float4*)d_out, n);
}

// round 13
// speedup vs baseline: 1.1075x; 1.0239x over previous
#include <cuda_runtime.h>

// Closed form of the 4-qubit circuit (derived R0, verified):
//   theta_i = x[b,i] + w[i],  c_i = cos(2*theta_i)
//   out[b] = { c1*c2*c3, c0*c1, c0*c1*c2, c0*c1*c2*c3 }
//
// R13: keeper body (flat 1-float4/thread, 16 regs) with 1024-thread CTAs
// (2048 blocks instead of 8192) — probes the launch-ramp component T_ovh,
// the last unexplored axis. 4x fewer CTA launch commands; still full
// occupancy (2 CTAs x 32 warps per SM).

__device__ __forceinline__ float4 proc(float4 xv, float w0, float w1,
                                       float w2, float w3)
{
    float c0 = __cosf(fmaf(2.0f, xv.x, w0));
    float c1 = __cosf(fmaf(2.0f, xv.y, w1));
    float c2 = __cosf(fmaf(2.0f, xv.z, w2));
    float c3 = __cosf(fmaf(2.0f, xv.w, w3));
    float t01  = c0 * c1;
    float t012 = t01 * c2;
    float4 o;
    o.x = c1 * c2 * c3;
    o.y = t01;
    o.z = t012;
    o.w = t012 * c3;
    return o;
}

__global__ void __launch_bounds__(1024)
hilbert_flat_big(const float4* __restrict__ x4,
                 const float* __restrict__ w,
                 float4* __restrict__ out4, int n)
{
    int i = blockIdx.x * 1024 + threadIdx.x;
    if (i >= n) return;
    float w0 = 2.0f * w[0], w1 = 2.0f * w[1];
    float w2 = 2.0f * w[2], w3 = 2.0f * w[3];
    out4[i] = proc(x4[i], w0, w1, w2, w3);
}

extern "C" void kernel_launch(void* const* d_in, const int* in_sizes, int n_in,
                              void* d_out, int out_size)
{
    const float* x = (const float*)d_in[0];
    const float* w = (const float*)d_in[1];
    int nx = in_sizes[0];
    if (n_in >= 2 && in_sizes[0] < in_sizes[1]) {
        x = (const float*)d_in[1];
        w = (const float*)d_in[0];
        nx = in_sizes[1];
    }

    int n = nx / 4;  // float4 count (= batch)
    int threads = 1024;
    int blocks = (n + threads - 1) / threads;   // 2048 for BATCH=2^21

    hilbert_flat_big<<<blocks, threads>>>(
        (const float4*)x, w, (float4*)d_out, n);
}